// round 13
// baseline (speedup 1.0000x reference)
#include <cuda_runtime.h>
#include <cstdint>

#define NN 50000
#define EE 20000
#define MM 320000
#define HH 4
#define KD 256
#define NC 384   // 256 V | 128 hid

// ---------------- static scratch ----------------
__device__ float    g_C[(size_t)NN * NC];
__device__ float    g_h[(size_t)NN * KD];
__device__ float    g_p[NN * 12];
__device__ float    g_aw[MM * 4];
__device__ float    g_ef[(size_t)EE * 256];
__device__ int      g_et[MM];
__device__ int      g_ecnt[EE];
__device__ int      g_estart[EE + 1];
__device__ int      g_ecur[EE];
__device__ int      g_pbe[MM];
__device__ int      g_ncnt[NN];
__device__ int      g_nstart[NN + 1];
__device__ int      g_ncur[NN];
__device__ int      g_pbn[MM];
__device__ float    g_W[NC * KD];
__device__ float    g_stq[HH * 3 * 32];
__device__ float    g_qe[12 * 256];
__device__ int      g_bsum[2][64];

#define MMATF32(d, a, b0, b1) \
  asm volatile("mma.sync.aligned.m16n8k8.row.col.f32.tf32.tf32.f32 " \
    "{%0,%1,%2,%3}, {%4,%5,%6,%7}, {%8,%9}, {%0,%1,%2,%3};" \
    : "+f"((d)[0]), "+f"((d)[1]), "+f"((d)[2]), "+f"((d)[3]) \
    : "r"((a)[0]), "r"((a)[1]), "r"((a)[2]), "r"((a)[3]), "r"(b0), "r"(b1))

__device__ __forceinline__ uint32_t f2tf32(float x) {
  uint32_t u;
  asm("cvt.rna.tf32.f32 %0, %1;" : "=r"(u) : "f"(x));
  return u;
}

// ---------------- CSR build ----------------
__global__ void zero_counts_kernel() {
  int i = blockIdx.x * blockDim.x + threadIdx.x;
  if (i < EE) g_ecnt[i] = 0;
  if (i < NN) g_ncnt[i] = 0;
}

__global__ void hist_kernel(const int* __restrict__ ni, const int* __restrict__ ei,
                            const int* __restrict__ etype) {
  int m = blockIdx.x * blockDim.x + threadIdx.x;
  if (m >= MM) return;
  int e = ei[m];
  atomicAdd(&g_ecnt[e], 1);
  atomicAdd(&g_ncnt[ni[m]], 1);
  g_et[m] = etype[e];
}

__global__ void scanA_kernel(int which) {
  __shared__ int sh[1024];
  const int* cnt = which ? g_ncnt : g_ecnt;
  int* start = which ? g_nstart : g_estart;
  int n = which ? NN : EE;
  int i = blockIdx.x * 1024 + threadIdx.x;
  int v = (i < n) ? cnt[i] : 0;
  sh[threadIdx.x] = v;
  __syncthreads();
  for (int off = 1; off < 1024; off <<= 1) {
    int t = (threadIdx.x >= (unsigned)off) ? sh[threadIdx.x - off] : 0;
    __syncthreads();
    sh[threadIdx.x] += t;
    __syncthreads();
  }
  if (i < n) start[i] = sh[threadIdx.x] - v;
  if (threadIdx.x == 1023) g_bsum[which][blockIdx.x] = sh[1023];
}

__global__ void scanB_kernel(int which, int nblk) {
  if (threadIdx.x) return;
  int* start = which ? g_nstart : g_estart;
  int n = which ? NN : EE;
  int run = 0;
  for (int b = 0; b < nblk; ++b) { int t = g_bsum[which][b]; g_bsum[which][b] = run; run += t; }
  start[n] = run;
}

__global__ void scanC_kernel(int which) {
  int* start = which ? g_nstart : g_estart;
  int* cur = which ? g_ncur : g_ecur;
  int n = which ? NN : EE;
  int i = blockIdx.x * 1024 + threadIdx.x;
  if (i < n) {
    int s = start[i] + g_bsum[which][blockIdx.x];
    start[i] = s;
    cur[i] = s;
  }
}

__global__ void fill_kernel(const int* __restrict__ ni, const int* __restrict__ ei) {
  int m = blockIdx.x * blockDim.x + threadIdx.x;
  if (m >= MM) return;
  int pe = atomicAdd(&g_ecur[ei[m]], 1);
  g_pbe[pe] = m;
  int pn = atomicAdd(&g_ncur[ni[m]], 1);
  g_pbn[pn] = m;
}

__global__ void segsort_kernel(int which) {
  int s = blockIdx.x * blockDim.x + threadIdx.x;
  const int* start = which ? g_nstart : g_estart;
  int* list = which ? g_pbn : g_pbe;
  int nseg = which ? NN : EE;
  if (s >= nseg) return;
  int a = start[s], b = start[s + 1];
  for (int i = a; i < b - 1; ++i) {
    int mi = i, mv = list[i];
    for (int j = i + 1; j < b; ++j) {
      int v = list[j];
      if (v < mv) { mv = v; mi = j; }
    }
    list[mi] = list[i];
    list[i] = mv;
  }
}

// ---------------- per-layer weight prep (merged qe + stq) ----------------
__global__ void prep_kernel(const float* __restrict__ ec, const float* __restrict__ wq,
                            const float* __restrict__ tq, const float* __restrict__ w1,
                            const float* __restrict__ b1, int l) {
  int bid = blockIdx.x;
  if (bid < 12) {
    __shared__ float s_ec[64];
    int h = bid / 3, t = bid % 3;
    int c = threadIdx.x;
    if (c < 64) s_ec[c] = ec[((l * HH + h) * 3 + t) * 64 + c];
    __syncthreads();
    if (c < 256) {
      const float* wr = wq + ((size_t)(l * HH + h) * 64) * 256 + c;
      float s = 0.f;
      for (int d = 0; d < 64; ++d) s += s_ec[d] * wr[(size_t)d * 256];
      g_qe[bid * 256 + c] = s;
    }
  } else {
    int tid = threadIdx.x;
    if (tid >= 384) return;
    int h = tid / 96, rem = tid % 96, t = rem / 32, k = rem & 31;
    float s = b1[(l * HH + h) * 32 + k];
    const float* tr = tq + ((l * HH + h) * 3 + t) * 64;
    const float* wr = w1 + (((size_t)l * HH + h) * 32 + k) * 320 + 256;
    for (int d = 0; d < 64; ++d) s += tr[d] * wr[d];
    g_stq[(h * 3 + t) * 32 + k] = s;
  }
}

// store g_W pre-rounded to tf32 (GEMM B path skips cvt; idempotent math)
__global__ void build_w_kernel(const float* __restrict__ wv, const float* __restrict__ w1,
                               int l) {
  int idx = blockIdx.x * blockDim.x + threadIdx.x;
  if (idx >= NC * KD) return;
  int r = idx >> 8, c = idx & 255;
  float v;
  if (r < 256) v = wv[((size_t)l * 256 + r) * 256 + c];
  else {
    int hk = r - 256;
    v = w1[(((size_t)l * HH + (hk >> 5)) * 32 + (hk & 31)) * 320 + c];
  }
  g_W[idx] = __uint_as_float(f2tf32(v));
}

// ---------------- tf32 mma GEMM: g_C[N,384] = X[N,256] * g_W^T ----------------
// CTA 128(M) x 128(N), 8 warps (4x2), warp tile 32x64, k-chunk 32, single buffer.
__global__ __launch_bounds__(256, 2) void gemm_tf32_kernel(const float* __restrict__ xin,
                                                           int l) {
  const float* __restrict__ X = l ? g_h : xin;
  __shared__ uint32_t sA[128][36];
  __shared__ uint32_t sB[128][36];
  const int tid = threadIdx.x, lane = tid & 31, wid = tid >> 5;
  const int wm = wid >> 1, wn = wid & 1;
  const int g = lane >> 2, tg = lane & 3;
  const int row0 = blockIdx.y * 128, col0 = blockIdx.x * 128;

  float acc[2][8][4];
#pragma unroll
  for (int a = 0; a < 2; ++a)
#pragma unroll
    for (int b = 0; b < 8; ++b)
#pragma unroll
      for (int c = 0; c < 4; ++c) acc[a][b][c] = 0.f;

  float4 pa[4];
#pragma unroll
  for (int i = 0; i < 4; ++i) {
    int u = tid + i * 256, r = u >> 3, q = u & 7;
    int gr = row0 + r;
    pa[i] = (gr < NN) ? *(const float4*)(X + (size_t)gr * KD + q * 4)
                      : make_float4(0.f, 0.f, 0.f, 0.f);
  }

  for (int kc = 0; kc < 8; ++kc) {
#pragma unroll
    for (int i = 0; i < 4; ++i) {
      int u = tid + i * 256, r = u >> 3, q = u & 7;
      uint32_t* dst = &sA[r][q * 4];
      dst[0] = f2tf32(pa[i].x); dst[1] = f2tf32(pa[i].y);
      dst[2] = f2tf32(pa[i].z); dst[3] = f2tf32(pa[i].w);
    }
#pragma unroll
    for (int i = 0; i < 4; ++i) {
      int u = tid + i * 256, r = u >> 3, q = u & 7;
      float4 bv = *(const float4*)(g_W + (size_t)(col0 + r) * KD + kc * 32 + q * 4);
      uint32_t* dst = &sB[r][q * 4];
      dst[0] = __float_as_uint(bv.x); dst[1] = __float_as_uint(bv.y);
      dst[2] = __float_as_uint(bv.z); dst[3] = __float_as_uint(bv.w);
    }
    __syncthreads();
    if (kc < 7) {
#pragma unroll
      for (int i = 0; i < 4; ++i) {
        int u = tid + i * 256, r = u >> 3, q = u & 7;
        int gr = row0 + r;
        pa[i] = (gr < NN) ? *(const float4*)(X + (size_t)gr * KD + (kc + 1) * 32 + q * 4)
                          : make_float4(0.f, 0.f, 0.f, 0.f);
      }
    }
#pragma unroll
    for (int ks = 0; ks < 4; ++ks) {
      const int k0 = ks * 8;
      uint32_t af[2][4], bf[8][2];
#pragma unroll
      for (int mt = 0; mt < 2; ++mt) {
        int rowA = wm * 32 + mt * 16 + g;
        af[mt][0] = sA[rowA][k0 + tg];
        af[mt][1] = sA[rowA + 8][k0 + tg];
        af[mt][2] = sA[rowA][k0 + tg + 4];
        af[mt][3] = sA[rowA + 8][k0 + tg + 4];
      }
#pragma unroll
      for (int j = 0; j < 8; ++j) {
        int rowB = wn * 64 + j * 8 + g;
        bf[j][0] = sB[rowB][k0 + tg];
        bf[j][1] = sB[rowB][k0 + tg + 4];
      }
#pragma unroll
      for (int mt = 0; mt < 2; ++mt)
#pragma unroll
        for (int j = 0; j < 8; ++j)
          MMATF32(acc[mt][j], af[mt], bf[j][0], bf[j][1]);
    }
    __syncthreads();
  }

#pragma unroll
  for (int mt = 0; mt < 2; ++mt) {
    int rg = row0 + wm * 32 + mt * 16 + g;
#pragma unroll
    for (int j = 0; j < 8; ++j) {
      int c = col0 + wn * 64 + j * 8 + tg * 2;
      if (rg < NN)
        *(float2*)&g_C[(size_t)rg * NC + c] = make_float2(acc[mt][j][0], acc[mt][j][1]);
      if (rg + 8 < NN)
        *(float2*)&g_C[(size_t)(rg + 8) * NC + c] = make_float2(acc[mt][j][2], acc[mt][j][3]);
    }
  }
}

// ---------------- per-node gate + qe dots: 4 nodes per warp ----------------
__global__ __launch_bounds__(256) void k2_kernel(const float* __restrict__ w2,
                                                 const float* __restrict__ b2,
                                                 const int* __restrict__ node_types,
                                                 const float* __restrict__ xin, int l) {
  __shared__ float s_stq[HH * 3 * 32];
  __shared__ float s_w2[HH * 32];
  __shared__ float s_b2[HH];
  __shared__ float s_qe[12 * 256];
  int tid = threadIdx.x;
  for (int i = tid; i < HH * 3 * 32; i += 256) s_stq[i] = g_stq[i];
  for (int i = tid; i < HH * 32; i += 256) s_w2[i] = w2[l * HH * 32 + i];
  if (tid < HH) s_b2[tid] = b2[l * HH + tid];
  for (int i = tid; i < 12 * 256; i += 256) s_qe[i] = g_qe[i];
  __syncthreads();
  int warp = tid >> 5, lane = tid & 31;
  const float* hbase = l ? g_h : xin;
  for (int s = 0; s < 4; ++s) {
    int n = blockIdx.x * 32 + warp * 4 + s;
    if (n >= NN) return;
    int tn = node_types[n];
    const float* Crow = g_C + (size_t)n * NC;
    const float* hrow = hbase + (size_t)n * KD;
    float hr[8];
#pragma unroll
    for (int j = 0; j < 8; ++j) hr[j] = hrow[j * 32 + lane];
#pragma unroll
    for (int h = 0; h < HH; ++h) {
      float hv = Crow[256 + h * 32 + lane];
      float th = tanhf(hv + s_stq[(h * 3 + tn) * 32 + lane]) * s_w2[h * 32 + lane];
#pragma unroll
      for (int o = 16; o; o >>= 1) th += __shfl_xor_sync(0xFFFFFFFFu, th, o);
      float at = 1.f / (1.f + expf(-(th + s_b2[h])));
#pragma unroll
      for (int t = 0; t < 3; ++t) {
        const float* qr = &s_qe[(h * 3 + t) * 256];
        float sp = 0.f;
#pragma unroll
        for (int j = 0; j < 8; ++j) sp += hr[j] * qr[j * 32 + lane];
#pragma unroll
        for (int o = 16; o; o >>= 1) sp += __shfl_xor_sync(0xFFFFFFFFu, sp, o);
        if (lane == 0) {
          float lr = sp > 0.f ? sp : 0.2f * sp;
          g_p[(n * 3 + t) * 4 + h] = lr * at;
        }
      }
    }
  }
}

// ---------------- segment softmax: warp per edge ----------------
__global__ __launch_bounds__(256) void kE_kernel(const int* __restrict__ ni) {
  int e = (blockIdx.x * blockDim.x + threadIdx.x) >> 5;
  int lane = threadIdx.x & 31;
  if (e >= EE) return;
  int a = g_estart[e], b = g_estart[e + 1];
  int h = lane & 3, pi = lane >> 2;
  float v[8];
  int mm[8];
  float mx = -1e30f;
#pragma unroll
  for (int k = 0; k < 8; ++k) {
    int i = a + k * 8 + pi;
    int m = -1;
    float val = -1e30f;
    if (i < b) {
      m = g_pbe[i];
      int nn2 = ni[m], t = g_et[m];
      val = g_p[(nn2 * 3 + t) * 4 + h];
    }
    mm[k] = m;
    v[k] = val;
    mx = fmaxf(mx, val);
  }
#pragma unroll
  for (int o = 4; o < 32; o <<= 1) mx = fmaxf(mx, __shfl_xor_sync(0xFFFFFFFFu, mx, o));
  float s = 0.f;
#pragma unroll
  for (int k = 0; k < 8; ++k) {
    if (mm[k] >= 0) { v[k] = expf(v[k] - mx); s += v[k]; }
  }
#pragma unroll
  for (int o = 4; o < 32; o <<= 1) s += __shfl_xor_sync(0xFFFFFFFFu, s, o);
  float inv = 1.f / s;
#pragma unroll
  for (int k = 0; k < 8; ++k)
    if (mm[k] >= 0) g_aw[mm[k] * 4 + h] = v[k] * inv;
}

// ---------------- edge_feat: warp per edge, 4x unrolled (sequential order) ----------------
__global__ __launch_bounds__(256) void k5_kernel(const int* __restrict__ ni) {
  int e = (blockIdx.x * blockDim.x + threadIdx.x) >> 5;
  int lane = threadIdx.x & 31;
  if (e >= EE) return;
  int a = g_estart[e], b = g_estart[e + 1];
  int hh = lane >> 3;
  int c0 = lane * 8;
  float4 a0 = make_float4(0, 0, 0, 0), a1 = make_float4(0, 0, 0, 0);
  int i = a;
  for (; i + 3 < b; i += 4) {
    int m0 = g_pbe[i], m1 = g_pbe[i + 1], m2 = g_pbe[i + 2], m3 = g_pbe[i + 3];
    float w0 = g_aw[m0 * 4 + hh], w1 = g_aw[m1 * 4 + hh];
    float w2 = g_aw[m2 * 4 + hh], w3 = g_aw[m3 * 4 + hh];
    const float* V0 = g_C + (size_t)ni[m0] * NC + c0;
    const float* V1 = g_C + (size_t)ni[m1] * NC + c0;
    const float* V2 = g_C + (size_t)ni[m2] * NC + c0;
    const float* V3 = g_C + (size_t)ni[m3] * NC + c0;
    float4 p0 = *(const float4*)V0, p1 = *(const float4*)(V0 + 4);
    float4 q0 = *(const float4*)V1, q1 = *(const float4*)(V1 + 4);
    float4 r0 = *(const float4*)V2, r1 = *(const float4*)(V2 + 4);
    float4 s0 = *(const float4*)V3, s1 = *(const float4*)(V3 + 4);
    a0.x += w0 * p0.x; a0.y += w0 * p0.y; a0.z += w0 * p0.z; a0.w += w0 * p0.w;
    a1.x += w0 * p1.x; a1.y += w0 * p1.y; a1.z += w0 * p1.z; a1.w += w0 * p1.w;
    a0.x += w1 * q0.x; a0.y += w1 * q0.y; a0.z += w1 * q0.z; a0.w += w1 * q0.w;
    a1.x += w1 * q1.x; a1.y += w1 * q1.y; a1.z += w1 * q1.z; a1.w += w1 * q1.w;
    a0.x += w2 * r0.x; a0.y += w2 * r0.y; a0.z += w2 * r0.z; a0.w += w2 * r0.w;
    a1.x += w2 * r1.x; a1.y += w2 * r1.y; a1.z += w2 * r1.z; a1.w += w2 * r1.w;
    a0.x += w3 * s0.x; a0.y += w3 * s0.y; a0.z += w3 * s0.z; a0.w += w3 * s0.w;
    a1.x += w3 * s1.x; a1.y += w3 * s1.y; a1.z += w3 * s1.z; a1.w += w3 * s1.w;
  }
  for (; i < b; ++i) {
    int m = g_pbe[i];
    float w = g_aw[m * 4 + hh];
    const float* Vr = g_C + (size_t)ni[m] * NC + c0;
    float4 v0 = *(const float4*)Vr;
    float4 v1 = *(const float4*)(Vr + 4);
    a0.x += w * v0.x; a0.y += w * v0.y; a0.z += w * v0.z; a0.w += w * v0.w;
    a1.x += w * v1.x; a1.y += w * v1.y; a1.z += w * v1.z; a1.w += w * v1.w;
  }
  float* out = g_ef + (size_t)e * 256 + c0;
  *(float4*)out = a0;
  *(float4*)(out + 4) = a1;
}

// ---------------- node_feat + residual + LayerNorm, 4x unrolled ----------------
__global__ __launch_bounds__(256) void k6_kernel(const int* __restrict__ ei,
                                                 const float* __restrict__ xin,
                                                 const float* __restrict__ ln_g,
                                                 const float* __restrict__ ln_b,
                                                 float* __restrict__ dout, int l) {
  int n = (blockIdx.x * blockDim.x + threadIdx.x) >> 5;
  int lane = threadIdx.x & 31;
  if (n >= NN) return;
  const float* hin = l ? g_h : xin;
  float* hout = l ? dout : g_h;
  int hh = lane >> 3;
  int c0 = lane * 8;
  float4 a0 = make_float4(0, 0, 0, 0), a1 = make_float4(0, 0, 0, 0);
  int a = g_nstart[n], b = g_nstart[n + 1];
  int i = a;
  for (; i + 3 < b; i += 4) {
    int m0 = g_pbn[i], m1 = g_pbn[i + 1], m2 = g_pbn[i + 2], m3 = g_pbn[i + 3];
    float w0 = g_aw[m0 * 4 + hh], w1 = g_aw[m1 * 4 + hh];
    float w2 = g_aw[m2 * 4 + hh], w3 = g_aw[m3 * 4 + hh];
    const float* E0 = g_ef + (size_t)ei[m0] * 256 + c0;
    const float* E1 = g_ef + (size_t)ei[m1] * 256 + c0;
    const float* E2 = g_ef + (size_t)ei[m2] * 256 + c0;
    const float* E3 = g_ef + (size_t)ei[m3] * 256 + c0;
    float4 p0 = *(const float4*)E0, p1 = *(const float4*)(E0 + 4);
    float4 q0 = *(const float4*)E1, q1 = *(const float4*)(E1 + 4);
    float4 r0 = *(const float4*)E2, r1 = *(const float4*)(E2 + 4);
    float4 s0 = *(const float4*)E3, s1 = *(const float4*)(E3 + 4);
    a0.x += w0 * p0.x; a0.y += w0 * p0.y; a0.z += w0 * p0.z; a0.w += w0 * p0.w;
    a1.x += w0 * p1.x; a1.y += w0 * p1.y; a1.z += w0 * p1.z; a1.w += w0 * p1.w;
    a0.x += w1 * q0.x; a0.y += w1 * q0.y; a0.z += w1 * q0.z; a0.w += w1 * q0.w;
    a1.x += w1 * q1.x; a1.y += w1 * q1.y; a1.z += w1 * q1.z; a1.w += w1 * q1.w;
    a0.x += w2 * r0.x; a0.y += w2 * r0.y; a0.z += w2 * r0.z; a0.w += w2 * r0.w;
    a1.x += w2 * r1.x; a1.y += w2 * r1.y; a1.z += w2 * r1.z; a1.w += w2 * r1.w;
    a0.x += w3 * s0.x; a0.y += w3 * s0.y; a0.z += w3 * s0.z; a0.w += w3 * s0.w;
    a1.x += w3 * s1.x; a1.y += w3 * s1.y; a1.z += w3 * s1.z; a1.w += w3 * s1.w;
  }
  for (; i < b; ++i) {
    int m = g_pbn[i];
    float w = g_aw[m * 4 + hh];
    const float* Er = g_ef + (size_t)ei[m] * 256 + c0;
    float4 e0 = *(const float4*)Er;
    float4 e1 = *(const float4*)(Er + 4);
    a0.x += w * e0.x; a0.y += w * e0.y; a0.z += w * e0.z; a0.w += w * e0.w;
    a1.x += w * e1.x; a1.y += w * e1.y; a1.z += w * e1.z; a1.w += w * e1.w;
  }
  float v[8] = {a0.x, a0.y, a0.z, a0.w, a1.x, a1.y, a1.z, a1.w};
  const float* hr = hin + (size_t)n * KD + c0;
#pragma unroll
  for (int j = 0; j < 8; ++j) v[j] += hr[j];
  float s = 0.f;
#pragma unroll
  for (int j = 0; j < 8; ++j) s += v[j];
#pragma unroll
  for (int o = 16; o; o >>= 1) s += __shfl_xor_sync(0xFFFFFFFFu, s, o);
  float mu = s * (1.f / 256.f);
  float vs = 0.f;
#pragma unroll
  for (int j = 0; j < 8; ++j) { float d = v[j] - mu; vs += d * d; }
#pragma unroll
  for (int o = 16; o; o >>= 1) vs += __shfl_xor_sync(0xFFFFFFFFu, vs, o);
  float rs = rsqrtf(vs * (1.f / 256.f) + 1e-5f);
  float o8[8];
#pragma unroll
  for (int j = 0; j < 8; ++j)
    o8[j] = (v[j] - mu) * rs * ln_g[l * KD + c0 + j] + ln_b[l * KD + c0 + j];
  float* op = hout + (size_t)n * KD + c0;
  *(float4*)op = make_float4(o8[0], o8[1], o8[2], o8[3]);
  *(float4*)(op + 4) = make_float4(o8[4], o8[5], o8[6], o8[7]);
}

// ---------------- launcher ----------------
extern "C" void kernel_launch(void* const* d_in, const int* in_sizes, int n_in,
                              void* d_out, int out_size) {
  const float* x          = (const float*)d_in[0];
  const int*   node_types = (const int*)d_in[1];
  const int*   edge_type  = (const int*)d_in[2];
  const int*   node_idx   = (const int*)d_in[3];
  const int*   edge_idx   = (const int*)d_in[4];
  const float* tq         = (const float*)d_in[5];
  const float* w1         = (const float*)d_in[6];
  const float* b1         = (const float*)d_in[7];
  const float* w2         = (const float*)d_in[8];
  const float* b2         = (const float*)d_in[9];
  const float* wq         = (const float*)d_in[10];
  const float* wv         = (const float*)d_in[11];
  const float* ec         = (const float*)d_in[12];
  const float* ln_g       = (const float*)d_in[13];
  const float* ln_b       = (const float*)d_in[14];
  float* out = (float*)d_out;

  const int TB = 256;
  int gMax = (NN + TB - 1) / TB;
  int gM   = (MM + TB - 1) / TB;
  int nbE = (EE + 1023) / 1024, nbN = (NN + 1023) / 1024;

  zero_counts_kernel<<<gMax, TB>>>();
  hist_kernel<<<gM, TB>>>(node_idx, edge_idx, edge_type);
  scanA_kernel<<<nbE, 1024>>>(0);
  scanB_kernel<<<1, 32>>>(0, nbE);
  scanC_kernel<<<nbE, 1024>>>(0);
  scanA_kernel<<<nbN, 1024>>>(1);
  scanB_kernel<<<1, 32>>>(1, nbN);
  scanC_kernel<<<nbN, 1024>>>(1);
  fill_kernel<<<gM, TB>>>(node_idx, edge_idx);
  segsort_kernel<<<(EE + TB - 1) / TB, TB>>>(0);
  segsort_kernel<<<(NN + TB - 1) / TB, TB>>>(1);

  for (int l = 0; l < 2; ++l) {
    prep_kernel<<<13, 384>>>(ec, wq, tq, w1, b1, l);
    build_w_kernel<<<(NC * KD + TB - 1) / TB, TB>>>(wv, w1, l);
    dim3 gg(NC / 128, (NN + 127) / 128);
    gemm_tf32_kernel<<<gg, 256>>>(x, l);
    k2_kernel<<<(NN + 31) / 32, 256>>>(w2, b2, node_types, x, l);
    kE_kernel<<<(EE + 7) / 8, 256>>>(node_idx);
    k5_kernel<<<(EE + 7) / 8, 256>>>(node_idx);
    k6_kernel<<<(NN + 7) / 8, 256>>>(edge_idx, x, ln_g, ln_b, out, l);
  }
}

// round 14
// speedup vs baseline: 1.0138x; 1.0138x over previous
#include <cuda_runtime.h>
#include <cstdint>

#define NN 50000
#define EE 20000
#define MM 320000
#define HH 4
#define KD 256
#define NC 384   // 256 V | 128 hid

// ---------------- static scratch ----------------
__device__ float    g_C[(size_t)NN * NC];
__device__ float    g_h[(size_t)NN * KD];
__device__ float    g_p[NN * 12];
__device__ float    g_aw[MM * 4];
__device__ float    g_ef[(size_t)EE * 256];
__device__ int      g_et[MM];
__device__ int      g_ecnt[EE];
__device__ int      g_estart[EE + 1];
__device__ int      g_ecur[EE];
__device__ int      g_pbe[MM];
__device__ int      g_ncnt[NN];
__device__ int      g_nstart[NN + 1];
__device__ int      g_ncur[NN];
__device__ int      g_pbn[MM];
__device__ float    g_W[NC * KD];
__device__ float    g_stq[HH * 3 * 32];
__device__ float    g_qe[12 * 256];
__device__ int      g_bsum[2][64];

#define MMATF32(d, a, b0, b1) \
  asm volatile("mma.sync.aligned.m16n8k8.row.col.f32.tf32.tf32.f32 " \
    "{%0,%1,%2,%3}, {%4,%5,%6,%7}, {%8,%9}, {%0,%1,%2,%3};" \
    : "+f"((d)[0]), "+f"((d)[1]), "+f"((d)[2]), "+f"((d)[3]) \
    : "r"((a)[0]), "r"((a)[1]), "r"((a)[2]), "r"((a)[3]), "r"(b0), "r"(b1))

__device__ __forceinline__ uint32_t f2tf32(float x) {
  uint32_t u;
  asm("cvt.rna.tf32.f32 %0, %1;" : "=r"(u) : "f"(x));
  return u;
}

// ---------------- CSR build ----------------
__global__ void zero_counts_kernel() {
  int i = blockIdx.x * blockDim.x + threadIdx.x;
  if (i < EE) g_ecnt[i] = 0;
  if (i < NN) g_ncnt[i] = 0;
}

__global__ void hist_kernel(const int* __restrict__ ni, const int* __restrict__ ei,
                            const int* __restrict__ etype) {
  int m = blockIdx.x * blockDim.x + threadIdx.x;
  if (m >= MM) return;
  int e = ei[m];
  atomicAdd(&g_ecnt[e], 1);
  atomicAdd(&g_ncnt[ni[m]], 1);
  g_et[m] = etype[e];
}

__global__ void scanA_kernel(int which) {
  __shared__ int sh[1024];
  const int* cnt = which ? g_ncnt : g_ecnt;
  int* start = which ? g_nstart : g_estart;
  int n = which ? NN : EE;
  int i = blockIdx.x * 1024 + threadIdx.x;
  int v = (i < n) ? cnt[i] : 0;
  sh[threadIdx.x] = v;
  __syncthreads();
  for (int off = 1; off < 1024; off <<= 1) {
    int t = (threadIdx.x >= (unsigned)off) ? sh[threadIdx.x - off] : 0;
    __syncthreads();
    sh[threadIdx.x] += t;
    __syncthreads();
  }
  if (i < n) start[i] = sh[threadIdx.x] - v;
  if (threadIdx.x == 1023) g_bsum[which][blockIdx.x] = sh[1023];
}

__global__ void scanB_kernel(int which, int nblk) {
  if (threadIdx.x) return;
  int* start = which ? g_nstart : g_estart;
  int n = which ? NN : EE;
  int run = 0;
  for (int b = 0; b < nblk; ++b) { int t = g_bsum[which][b]; g_bsum[which][b] = run; run += t; }
  start[n] = run;
}

__global__ void scanC_kernel(int which) {
  int* start = which ? g_nstart : g_estart;
  int* cur = which ? g_ncur : g_ecur;
  int n = which ? NN : EE;
  int i = blockIdx.x * 1024 + threadIdx.x;
  if (i < n) {
    int s = start[i] + g_bsum[which][blockIdx.x];
    start[i] = s;
    cur[i] = s;
  }
}

__global__ void fill_kernel(const int* __restrict__ ni, const int* __restrict__ ei) {
  int m = blockIdx.x * blockDim.x + threadIdx.x;
  if (m >= MM) return;
  int pe = atomicAdd(&g_ecur[ei[m]], 1);
  g_pbe[pe] = m;
  int pn = atomicAdd(&g_ncur[ni[m]], 1);
  g_pbn[pn] = m;
}

__global__ void segsort_kernel(int which) {
  int s = blockIdx.x * blockDim.x + threadIdx.x;
  const int* start = which ? g_nstart : g_estart;
  int* list = which ? g_pbn : g_pbe;
  int nseg = which ? NN : EE;
  if (s >= nseg) return;
  int a = start[s], b = start[s + 1];
  for (int i = a; i < b - 1; ++i) {
    int mi = i, mv = list[i];
    for (int j = i + 1; j < b; ++j) {
      int v = list[j];
      if (v < mv) { mv = v; mi = j; }
    }
    list[mi] = list[i];
    list[i] = mv;
  }
}

// ---------------- per-layer weight prep (merged qe + stq) ----------------
__global__ void prep_kernel(const float* __restrict__ ec, const float* __restrict__ wq,
                            const float* __restrict__ tq, const float* __restrict__ w1,
                            const float* __restrict__ b1, int l) {
  int bid = blockIdx.x;
  if (bid < 12) {
    __shared__ float s_ec[64];
    int h = bid / 3, t = bid % 3;
    int c = threadIdx.x;
    if (c < 64) s_ec[c] = ec[((l * HH + h) * 3 + t) * 64 + c];
    __syncthreads();
    if (c < 256) {
      const float* wr = wq + ((size_t)(l * HH + h) * 64) * 256 + c;
      float s = 0.f;
      for (int d = 0; d < 64; ++d) s += s_ec[d] * wr[(size_t)d * 256];
      g_qe[bid * 256 + c] = s;
    }
  } else {
    int tid = threadIdx.x;
    if (tid >= 384) return;
    int h = tid / 96, rem = tid % 96, t = rem / 32, k = rem & 31;
    float s = b1[(l * HH + h) * 32 + k];
    const float* tr = tq + ((l * HH + h) * 3 + t) * 64;
    const float* wr = w1 + (((size_t)l * HH + h) * 32 + k) * 320 + 256;
    for (int d = 0; d < 64; ++d) s += tr[d] * wr[d];
    g_stq[(h * 3 + t) * 32 + k] = s;
  }
}

__global__ void build_w_kernel(const float* __restrict__ wv, const float* __restrict__ w1,
                               int l) {
  int idx = blockIdx.x * blockDim.x + threadIdx.x;
  if (idx >= NC * KD) return;
  int r = idx >> 8, c = idx & 255;
  float v;
  if (r < 256) v = wv[((size_t)l * 256 + r) * 256 + c];
  else {
    int hk = r - 256;
    v = w1[(((size_t)l * HH + (hk >> 5)) * 32 + (hk & 31)) * 320 + c];
  }
  g_W[idx] = v;
}

// ---------------- tf32 mma GEMM: g_C[N,384] = X[N,256] * g_W^T ----------------
// CTA 128(M) x 128(N), 8 warps (4x2), warp tile 32x64, k-chunk 32, single buffer.
__global__ __launch_bounds__(256, 2) void gemm_tf32_kernel(const float* __restrict__ xin,
                                                           int l) {
  const float* __restrict__ X = l ? g_h : xin;
  __shared__ uint32_t sA[128][36];
  __shared__ uint32_t sB[128][36];
  const int tid = threadIdx.x, lane = tid & 31, wid = tid >> 5;
  const int wm = wid >> 1, wn = wid & 1;
  const int g = lane >> 2, tg = lane & 3;
  const int row0 = blockIdx.y * 128, col0 = blockIdx.x * 128;

  float acc[2][8][4];
#pragma unroll
  for (int a = 0; a < 2; ++a)
#pragma unroll
    for (int b = 0; b < 8; ++b)
#pragma unroll
      for (int c = 0; c < 4; ++c) acc[a][b][c] = 0.f;

  float4 pa[4];
#pragma unroll
  for (int i = 0; i < 4; ++i) {
    int u = tid + i * 256, r = u >> 3, q = u & 7;
    int gr = row0 + r;
    pa[i] = (gr < NN) ? *(const float4*)(X + (size_t)gr * KD + q * 4)
                      : make_float4(0.f, 0.f, 0.f, 0.f);
  }

  for (int kc = 0; kc < 8; ++kc) {
#pragma unroll
    for (int i = 0; i < 4; ++i) {
      int u = tid + i * 256, r = u >> 3, q = u & 7;
      uint32_t* dst = &sA[r][q * 4];
      dst[0] = f2tf32(pa[i].x); dst[1] = f2tf32(pa[i].y);
      dst[2] = f2tf32(pa[i].z); dst[3] = f2tf32(pa[i].w);
    }
#pragma unroll
    for (int i = 0; i < 4; ++i) {
      int u = tid + i * 256, r = u >> 3, q = u & 7;
      float4 bv = *(const float4*)(g_W + (size_t)(col0 + r) * KD + kc * 32 + q * 4);
      uint32_t* dst = &sB[r][q * 4];
      dst[0] = f2tf32(bv.x); dst[1] = f2tf32(bv.y);
      dst[2] = f2tf32(bv.z); dst[3] = f2tf32(bv.w);
    }
    __syncthreads();
    if (kc < 7) {
#pragma unroll
      for (int i = 0; i < 4; ++i) {
        int u = tid + i * 256, r = u >> 3, q = u & 7;
        int gr = row0 + r;
        pa[i] = (gr < NN) ? *(const float4*)(X + (size_t)gr * KD + (kc + 1) * 32 + q * 4)
                          : make_float4(0.f, 0.f, 0.f, 0.f);
      }
    }
#pragma unroll
    for (int ks = 0; ks < 4; ++ks) {
      const int k0 = ks * 8;
      uint32_t af[2][4], bf[8][2];
#pragma unroll
      for (int mt = 0; mt < 2; ++mt) {
        int rowA = wm * 32 + mt * 16 + g;
        af[mt][0] = sA[rowA][k0 + tg];
        af[mt][1] = sA[rowA + 8][k0 + tg];
        af[mt][2] = sA[rowA][k0 + tg + 4];
        af[mt][3] = sA[rowA + 8][k0 + tg + 4];
      }
#pragma unroll
      for (int j = 0; j < 8; ++j) {
        int rowB = wn * 64 + j * 8 + g;
        bf[j][0] = sB[rowB][k0 + tg];
        bf[j][1] = sB[rowB][k0 + tg + 4];
      }
#pragma unroll
      for (int mt = 0; mt < 2; ++mt)
#pragma unroll
        for (int j = 0; j < 8; ++j)
          MMATF32(acc[mt][j], af[mt], bf[j][0], bf[j][1]);
    }
    __syncthreads();
  }

#pragma unroll
  for (int mt = 0; mt < 2; ++mt) {
    int rg = row0 + wm * 32 + mt * 16 + g;
#pragma unroll
    for (int j = 0; j < 8; ++j) {
      int c = col0 + wn * 64 + j * 8 + tg * 2;
      if (rg < NN)
        *(float2*)&g_C[(size_t)rg * NC + c] = make_float2(acc[mt][j][0], acc[mt][j][1]);
      if (rg + 8 < NN)
        *(float2*)&g_C[(size_t)(rg + 8) * NC + c] = make_float2(acc[mt][j][2], acc[mt][j][3]);
    }
  }
}

// ---------------- per-node gate + qe dots -> p[n][t][h] ----------------
__global__ __launch_bounds__(256) void k2_kernel(const float* __restrict__ w2,
                                                 const float* __restrict__ b2,
                                                 const int* __restrict__ node_types,
                                                 const float* __restrict__ xin, int l) {
  __shared__ float s_stq[HH * 3 * 32];
  __shared__ float s_w2[HH * 32];
  __shared__ float s_b2[HH];
  __shared__ float s_qe[12 * 256];
  int tid = threadIdx.x;
  for (int i = tid; i < HH * 3 * 32; i += 256) s_stq[i] = g_stq[i];
  for (int i = tid; i < HH * 32; i += 256) s_w2[i] = w2[l * HH * 32 + i];
  if (tid < HH) s_b2[tid] = b2[l * HH + tid];
  for (int i = tid; i < 12 * 256; i += 256) s_qe[i] = g_qe[i];
  __syncthreads();
  int warp = tid >> 5, lane = tid & 31;
  int n = blockIdx.x * 8 + warp;
  if (n >= NN) return;
  int tn = node_types[n];
  const float* Crow = g_C + (size_t)n * NC;
  const float* hrow = (l ? g_h : xin) + (size_t)n * KD;
  float hr[8];
#pragma unroll
  for (int j = 0; j < 8; ++j) hr[j] = hrow[j * 32 + lane];
#pragma unroll
  for (int h = 0; h < HH; ++h) {
    float hv = Crow[256 + h * 32 + lane];
    float th = tanhf(hv + s_stq[(h * 3 + tn) * 32 + lane]) * s_w2[h * 32 + lane];
#pragma unroll
    for (int o = 16; o; o >>= 1) th += __shfl_xor_sync(0xFFFFFFFFu, th, o);
    float at = 1.f / (1.f + expf(-(th + s_b2[h])));
#pragma unroll
    for (int t = 0; t < 3; ++t) {
      const float* qr = &s_qe[(h * 3 + t) * 256];
      float sp = 0.f;
#pragma unroll
      for (int j = 0; j < 8; ++j) sp += hr[j] * qr[j * 32 + lane];
#pragma unroll
      for (int o = 16; o; o >>= 1) sp += __shfl_xor_sync(0xFFFFFFFFu, sp, o);
      if (lane == 0) {
        float lr = sp > 0.f ? sp : 0.2f * sp;
        g_p[(n * 3 + t) * 4 + h] = lr * at;
      }
    }
  }
}

// ---------------- fused softmax + edge_feat: warp per edge ----------------
// Phase 1 computes softmax weights (capacity 64 pairs/edge), stages them in
// warp-private SMEM AND writes g_aw (needed by k6). Phase 2 gathers V with
// weights read from SMEM (no global round-trip). Accumulation order identical
// to the unfused version.
__global__ __launch_bounds__(256) void kE5_kernel(const int* __restrict__ ni) {
  __shared__ float s_w[8][256];   // [warp][pair*4 + head]
  int e = (blockIdx.x * blockDim.x + threadIdx.x) >> 5;
  int warp = (threadIdx.x >> 5);
  int lane = threadIdx.x & 31;
  if (e >= EE) return;
  int a = g_estart[e], b = g_estart[e + 1];
  // ---- phase 1: softmax (lane = pair_slot*4 + head) ----
  {
    int h = lane & 3, pi = lane >> 2;
    float v[8];
    int mm[8];
    float mx = -1e30f;
#pragma unroll
    for (int k = 0; k < 8; ++k) {
      int i = a + k * 8 + pi;
      int m = -1;
      float val = -1e30f;
      if (i < b) {
        m = g_pbe[i];
        int nn2 = ni[m], t = g_et[m];
        val = g_p[(nn2 * 3 + t) * 4 + h];
      }
      mm[k] = m;
      v[k] = val;
      mx = fmaxf(mx, val);
    }
#pragma unroll
    for (int o = 4; o < 32; o <<= 1) mx = fmaxf(mx, __shfl_xor_sync(0xFFFFFFFFu, mx, o));
    float s = 0.f;
#pragma unroll
    for (int k = 0; k < 8; ++k) {
      if (mm[k] >= 0) { v[k] = expf(v[k] - mx); s += v[k]; }
    }
#pragma unroll
    for (int o = 4; o < 32; o <<= 1) s += __shfl_xor_sync(0xFFFFFFFFu, s, o);
    float inv = 1.f / s;
#pragma unroll
    for (int k = 0; k < 8; ++k) {
      if (mm[k] >= 0) {
        float wgt = v[k] * inv;
        g_aw[mm[k] * 4 + h] = wgt;
        s_w[warp][(k * 8 + pi) * 4 + h] = wgt;
      }
    }
  }
  __syncwarp();
  // ---- phase 2: gather V rows (weights from SMEM) ----
  {
    int hh = lane >> 3;
    int c0 = lane * 8;
    float4 a0 = make_float4(0, 0, 0, 0), a1 = make_float4(0, 0, 0, 0);
    for (int i = a; i < b; ++i) {
      int m = g_pbe[i];
      float w = s_w[warp][(i - a) * 4 + hh];
      const float* Vr = g_C + (size_t)ni[m] * NC + c0;
      float4 v0 = *(const float4*)Vr;
      float4 v1 = *(const float4*)(Vr + 4);
      a0.x += w * v0.x; a0.y += w * v0.y; a0.z += w * v0.z; a0.w += w * v0.w;
      a1.x += w * v1.x; a1.y += w * v1.y; a1.z += w * v1.z; a1.w += w * v1.w;
    }
    float* out = g_ef + (size_t)e * 256 + c0;
    *(float4*)out = a0;
    *(float4*)(out + 4) = a1;
  }
}

// ---------------- node_feat + residual + LayerNorm ----------------
__global__ __launch_bounds__(256) void k6_kernel(const int* __restrict__ ei,
                                                 const float* __restrict__ xin,
                                                 const float* __restrict__ ln_g,
                                                 const float* __restrict__ ln_b,
                                                 float* __restrict__ dout, int l) {
  int n = (blockIdx.x * blockDim.x + threadIdx.x) >> 5;
  int lane = threadIdx.x & 31;
  if (n >= NN) return;
  const float* hin = l ? g_h : xin;
  float* hout = l ? dout : g_h;
  int hh = lane >> 3;
  int c0 = lane * 8;
  float v[8];
#pragma unroll
  for (int j = 0; j < 8; ++j) v[j] = 0.f;
  int b = g_nstart[n + 1];
  for (int i = g_nstart[n]; i < b; ++i) {
    int m = g_pbn[i];
    float w = g_aw[m * 4 + hh];
    const float* Er = g_ef + (size_t)ei[m] * 256 + c0;
    float4 e0 = *(const float4*)Er;
    float4 e1 = *(const float4*)(Er + 4);
    v[0] += w * e0.x; v[1] += w * e0.y; v[2] += w * e0.z; v[3] += w * e0.w;
    v[4] += w * e1.x; v[5] += w * e1.y; v[6] += w * e1.z; v[7] += w * e1.w;
  }
  const float* hr = hin + (size_t)n * KD + c0;
#pragma unroll
  for (int j = 0; j < 8; ++j) v[j] += hr[j];
  float s = 0.f;
#pragma unroll
  for (int j = 0; j < 8; ++j) s += v[j];
#pragma unroll
  for (int o = 16; o; o >>= 1) s += __shfl_xor_sync(0xFFFFFFFFu, s, o);
  float mu = s * (1.f / 256.f);
  float vs = 0.f;
#pragma unroll
  for (int j = 0; j < 8; ++j) { float d = v[j] - mu; vs += d * d; }
#pragma unroll
  for (int o = 16; o; o >>= 1) vs += __shfl_xor_sync(0xFFFFFFFFu, vs, o);
  float rs = rsqrtf(vs * (1.f / 256.f) + 1e-5f);
  float o8[8];
#pragma unroll
  for (int j = 0; j < 8; ++j)
    o8[j] = (v[j] - mu) * rs * ln_g[l * KD + c0 + j] + ln_b[l * KD + c0 + j];
  float* op = hout + (size_t)n * KD + c0;
  *(float4*)op = make_float4(o8[0], o8[1], o8[2], o8[3]);
  *(float4*)(op + 4) = make_float4(o8[4], o8[5], o8[6], o8[7]);
}

// ---------------- launcher ----------------
// Launch order arranged so ncu (-s 5 -c 1) captures the GEMM (launch #6).
extern "C" void kernel_launch(void* const* d_in, const int* in_sizes, int n_in,
                              void* d_out, int out_size) {
  const float* x          = (const float*)d_in[0];
  const int*   node_types = (const int*)d_in[1];
  const int*   edge_type  = (const int*)d_in[2];
  const int*   node_idx   = (const int*)d_in[3];
  const int*   edge_idx   = (const int*)d_in[4];
  const float* tq         = (const float*)d_in[5];
  const float* w1         = (const float*)d_in[6];
  const float* b1         = (const float*)d_in[7];
  const float* w2         = (const float*)d_in[8];
  const float* b2         = (const float*)d_in[9];
  const float* wq         = (const float*)d_in[10];
  const float* wv         = (const float*)d_in[11];
  const float* ec         = (const float*)d_in[12];
  const float* ln_g       = (const float*)d_in[13];
  const float* ln_b       = (const float*)d_in[14];
  float* out = (float*)d_out;

  const int TB = 256;
  int gMax = (NN + TB - 1) / TB;
  int gM   = (MM + TB - 1) / TB;
  int nbE = (EE + 1023) / 1024, nbN = (NN + 1023) / 1024;
  dim3 gg(NC / 128, (NN + 127) / 128);

  // 1..5: CSR front half + layer-0 GEMM prep
  zero_counts_kernel<<<gMax, TB>>>();                         // 1
  hist_kernel<<<gM, TB>>>(node_idx, edge_idx, edge_type);     // 2
  build_w_kernel<<<(NC * KD + TB - 1) / TB, TB>>>(wv, w1, 0); // 3
  scanA_kernel<<<nbE, 1024>>>(0);                             // 4
  prep_kernel<<<13, 384>>>(ec, wq, tq, w1, b1, 0);            // 5
  gemm_tf32_kernel<<<gg, 256>>>(x, 0);                        // 6  <- ncu target
  // remaining CSR build
  scanB_kernel<<<1, 32>>>(0, nbE);
  scanC_kernel<<<nbE, 1024>>>(0);
  scanA_kernel<<<nbN, 1024>>>(1);
  scanB_kernel<<<1, 32>>>(1, nbN);
  scanC_kernel<<<nbN, 1024>>>(1);
  fill_kernel<<<gM, TB>>>(node_idx, edge_idx);
  segsort_kernel<<<(EE + TB - 1) / TB, TB>>>(0);
  segsort_kernel<<<(NN + TB - 1) / TB, TB>>>(1);
  // layer 0 rest
  k2_kernel<<<(NN + 7) / 8, 256>>>(w2, b2, node_types, x, 0);
  kE5_kernel<<<(EE + 7) / 8, 256>>>(node_idx);
  k6_kernel<<<(NN + 7) / 8, 256>>>(edge_idx, x, ln_g, ln_b, out, 0);
  // layer 1
  prep_kernel<<<13, 384>>>(ec, wq, tq, w1, b1, 1);
  build_w_kernel<<<(NC * KD + TB - 1) / TB, TB>>>(wv, w1, 1);
  gemm_tf32_kernel<<<gg, 256>>>(x, 1);
  k2_kernel<<<(NN + 7) / 8, 256>>>(w2, b2, node_types, x, 1);
  kE5_kernel<<<(EE + 7) / 8, 256>>>(node_idx);
  k6_kernel<<<(NN + 7) / 8, 256>>>(edge_idx, x, ln_g, ln_b, out, 1);
}

// round 15
// speedup vs baseline: 1.0554x; 1.0411x over previous
#include <cuda_runtime.h>
#include <cstdint>

#define NN 50000
#define EE 20000
#define MM 320000
#define HH 4
#define KD 256
#define NC 384   // 256 V | 128 hid
#define NBE 20   // ceil(EE/1024)
#define NBN 49   // ceil(NN/1024)

// ---------------- static scratch ----------------
__device__ float    g_C[(size_t)NN * NC];
__device__ float    g_h[(size_t)NN * KD];
__device__ float    g_p[NN * 12];
__device__ float    g_aw[MM * 4];
__device__ float    g_ef[(size_t)EE * 256];
__device__ int      g_et[MM];
__device__ int      g_ecnt[EE];
__device__ int      g_estart[EE + 1];
__device__ int      g_ecur[EE];
__device__ int      g_pbe[MM];
__device__ int      g_ncnt[NN];
__device__ int      g_nstart[NN + 1];
__device__ int      g_ncur[NN];
__device__ int      g_pbn[MM];
__device__ float    g_W[NC * KD];
__device__ float    g_stq[HH * 3 * 32];
__device__ float    g_qe[12 * 256];
__device__ int      g_bsum[2][64];

#define MMATF32(d, a, b0, b1) \
  asm volatile("mma.sync.aligned.m16n8k8.row.col.f32.tf32.tf32.f32 " \
    "{%0,%1,%2,%3}, {%4,%5,%6,%7}, {%8,%9}, {%0,%1,%2,%3};" \
    : "+f"((d)[0]), "+f"((d)[1]), "+f"((d)[2]), "+f"((d)[3]) \
    : "r"((a)[0]), "r"((a)[1]), "r"((a)[2]), "r"((a)[3]), "r"(b0), "r"(b1))

__device__ __forceinline__ uint32_t f2tf32(float x) {
  uint32_t u;
  asm("cvt.rna.tf32.f32 %0, %1;" : "=r"(u) : "f"(x));
  return u;
}

// ---------------- CSR build ----------------
__global__ void zero_counts_kernel() {
  int i = blockIdx.x * blockDim.x + threadIdx.x;
  if (i < EE) g_ecnt[i] = 0;
  if (i < NN) g_ncnt[i] = 0;
}

__global__ void hist_kernel(const int* __restrict__ ni, const int* __restrict__ ei,
                            const int* __restrict__ etype) {
  int m = blockIdx.x * blockDim.x + threadIdx.x;
  if (m >= MM) return;
  int e = ei[m];
  atomicAdd(&g_ecnt[e], 1);
  atomicAdd(&g_ncnt[ni[m]], 1);
  g_et[m] = etype[e];
}

// merged block-scan for edges (blocks 0..NBE-1) and nodes (blocks NBE..NBE+NBN-1)
__global__ void scanA2_kernel() {
  __shared__ int sh[1024];
  int which = (blockIdx.x < NBE) ? 0 : 1;
  int bid = which ? (blockIdx.x - NBE) : blockIdx.x;
  const int* cnt = which ? g_ncnt : g_ecnt;
  int* start = which ? g_nstart : g_estart;
  int n = which ? NN : EE;
  int i = bid * 1024 + threadIdx.x;
  int v = (i < n) ? cnt[i] : 0;
  sh[threadIdx.x] = v;
  __syncthreads();
  for (int off = 1; off < 1024; off <<= 1) {
    int t = (threadIdx.x >= (unsigned)off) ? sh[threadIdx.x - off] : 0;
    __syncthreads();
    sh[threadIdx.x] += t;
    __syncthreads();
  }
  if (i < n) start[i] = sh[threadIdx.x] - v;
  if (threadIdx.x == 1023) g_bsum[which][bid] = sh[1023];
}

// merged offset-apply; folds the tiny serial scan of g_bsum into each block,
// inits cursors, and writes start[n] total from the last block of each half.
__global__ void scanC2_kernel() {
  int which = (blockIdx.x < NBE) ? 0 : 1;
  int bid = which ? (blockIdx.x - NBE) : blockIdx.x;
  int nb = which ? NBN : NBE;
  int* start = which ? g_nstart : g_estart;
  int* cur = which ? g_ncur : g_ecur;
  int n = which ? NN : EE;
  int off = 0;
  for (int b = 0; b < bid; ++b) off += g_bsum[which][b];
  int i = bid * 1024 + threadIdx.x;
  if (i < n) {
    int s = start[i] + off;
    start[i] = s;
    cur[i] = s;
  }
  if (bid == nb - 1 && threadIdx.x == 0)
    start[n] = off + g_bsum[which][bid];
}

__global__ void fill_kernel(const int* __restrict__ ni, const int* __restrict__ ei) {
  int m = blockIdx.x * blockDim.x + threadIdx.x;
  if (m >= MM) return;
  int pe = atomicAdd(&g_ecur[ei[m]], 1);
  g_pbe[pe] = m;
  int pn = atomicAdd(&g_ncur[ni[m]], 1);
  g_pbn[pn] = m;
}

// merged per-segment selection sort: s < EE -> edge lists, else node lists
__global__ void segsort2_kernel() {
  int s = blockIdx.x * blockDim.x + threadIdx.x;
  if (s >= EE + NN) return;
  int which = (s >= EE);
  int seg = which ? (s - EE) : s;
  const int* start = which ? g_nstart : g_estart;
  int* list = which ? g_pbn : g_pbe;
  int a = start[seg], b = start[seg + 1];
  for (int i = a; i < b - 1; ++i) {
    int mi = i, mv = list[i];
    for (int j = i + 1; j < b; ++j) {
      int v = list[j];
      if (v < mv) { mv = v; mi = j; }
    }
    list[mi] = list[i];
    list[i] = mv;
  }
}

// ---------------- merged weight prep: build_w (blocks 0..255) + qe (256..267) + stq (268) ----------------
__global__ void prepW_kernel(const float* __restrict__ wv, const float* __restrict__ w1,
                             const float* __restrict__ ec, const float* __restrict__ wq,
                             const float* __restrict__ tq, const float* __restrict__ b1,
                             int l) {
  int bid = blockIdx.x;
  int tid = threadIdx.x;
  if (bid < 256) {
    int idx = bid * 384 + tid;   // NC*KD = 98304 = 256*384
    int r = idx >> 8, c = idx & 255;
    float v;
    if (r < 256) v = wv[((size_t)l * 256 + r) * 256 + c];
    else {
      int hk = r - 256;
      v = w1[(((size_t)l * HH + (hk >> 5)) * 32 + (hk & 31)) * 320 + c];
    }
    g_W[idx] = v;
  } else if (bid < 268) {
    __shared__ float s_ec[64];
    int ht = bid - 256;
    int h = ht / 3, t = ht % 3;
    if (tid < 64) s_ec[tid] = ec[((l * HH + h) * 3 + t) * 64 + tid];
    __syncthreads();
    if (tid < 256) {
      const float* wr = wq + ((size_t)(l * HH + h) * 64) * 256 + tid;
      float s = 0.f;
      for (int d = 0; d < 64; ++d) s += s_ec[d] * wr[(size_t)d * 256];
      g_qe[ht * 256 + tid] = s;
    }
  } else {
    if (tid >= 384) return;
    int h = tid / 96, rem = tid % 96, t = rem / 32, k = rem & 31;
    float s = b1[(l * HH + h) * 32 + k];
    const float* tr = tq + ((l * HH + h) * 3 + t) * 64;
    const float* wr = w1 + (((size_t)l * HH + h) * 32 + k) * 320 + 256;
    for (int d = 0; d < 64; ++d) s += tr[d] * wr[d];
    g_stq[(h * 3 + t) * 32 + k] = s;
  }
}

// ---------------- tf32 mma GEMM: g_C[N,384] = X[N,256] * g_W^T ----------------
// CTA 128(M) x 128(N), 8 warps (4x2), warp tile 32x64, k-chunk 32, single buffer.
__global__ __launch_bounds__(256, 2) void gemm_tf32_kernel(const float* __restrict__ xin,
                                                           int l) {
  const float* __restrict__ X = l ? g_h : xin;
  __shared__ uint32_t sA[128][36];
  __shared__ uint32_t sB[128][36];
  const int tid = threadIdx.x, lane = tid & 31, wid = tid >> 5;
  const int wm = wid >> 1, wn = wid & 1;
  const int g = lane >> 2, tg = lane & 3;
  const int row0 = blockIdx.y * 128, col0 = blockIdx.x * 128;

  float acc[2][8][4];
#pragma unroll
  for (int a = 0; a < 2; ++a)
#pragma unroll
    for (int b = 0; b < 8; ++b)
#pragma unroll
      for (int c = 0; c < 4; ++c) acc[a][b][c] = 0.f;

  float4 pa[4];
#pragma unroll
  for (int i = 0; i < 4; ++i) {
    int u = tid + i * 256, r = u >> 3, q = u & 7;
    int gr = row0 + r;
    pa[i] = (gr < NN) ? *(const float4*)(X + (size_t)gr * KD + q * 4)
                      : make_float4(0.f, 0.f, 0.f, 0.f);
  }

  for (int kc = 0; kc < 8; ++kc) {
#pragma unroll
    for (int i = 0; i < 4; ++i) {
      int u = tid + i * 256, r = u >> 3, q = u & 7;
      uint32_t* dst = &sA[r][q * 4];
      dst[0] = f2tf32(pa[i].x); dst[1] = f2tf32(pa[i].y);
      dst[2] = f2tf32(pa[i].z); dst[3] = f2tf32(pa[i].w);
    }
#pragma unroll
    for (int i = 0; i < 4; ++i) {
      int u = tid + i * 256, r = u >> 3, q = u & 7;
      float4 bv = *(const float4*)(g_W + (size_t)(col0 + r) * KD + kc * 32 + q * 4);
      uint32_t* dst = &sB[r][q * 4];
      dst[0] = f2tf32(bv.x); dst[1] = f2tf32(bv.y);
      dst[2] = f2tf32(bv.z); dst[3] = f2tf32(bv.w);
    }
    __syncthreads();
    if (kc < 7) {
#pragma unroll
      for (int i = 0; i < 4; ++i) {
        int u = tid + i * 256, r = u >> 3, q = u & 7;
        int gr = row0 + r;
        pa[i] = (gr < NN) ? *(const float4*)(X + (size_t)gr * KD + (kc + 1) * 32 + q * 4)
                          : make_float4(0.f, 0.f, 0.f, 0.f);
      }
    }
#pragma unroll
    for (int ks = 0; ks < 4; ++ks) {
      const int k0 = ks * 8;
      uint32_t af[2][4], bf[8][2];
#pragma unroll
      for (int mt = 0; mt < 2; ++mt) {
        int rowA = wm * 32 + mt * 16 + g;
        af[mt][0] = sA[rowA][k0 + tg];
        af[mt][1] = sA[rowA + 8][k0 + tg];
        af[mt][2] = sA[rowA][k0 + tg + 4];
        af[mt][3] = sA[rowA + 8][k0 + tg + 4];
      }
#pragma unroll
      for (int j = 0; j < 8; ++j) {
        int rowB = wn * 64 + j * 8 + g;
        bf[j][0] = sB[rowB][k0 + tg];
        bf[j][1] = sB[rowB][k0 + tg + 4];
      }
#pragma unroll
      for (int mt = 0; mt < 2; ++mt)
#pragma unroll
        for (int j = 0; j < 8; ++j)
          MMATF32(acc[mt][j], af[mt], bf[j][0], bf[j][1]);
    }
    __syncthreads();
  }

#pragma unroll
  for (int mt = 0; mt < 2; ++mt) {
    int rg = row0 + wm * 32 + mt * 16 + g;
#pragma unroll
    for (int j = 0; j < 8; ++j) {
      int c = col0 + wn * 64 + j * 8 + tg * 2;
      if (rg < NN)
        *(float2*)&g_C[(size_t)rg * NC + c] = make_float2(acc[mt][j][0], acc[mt][j][1]);
      if (rg + 8 < NN)
        *(float2*)&g_C[(size_t)(rg + 8) * NC + c] = make_float2(acc[mt][j][2], acc[mt][j][3]);
    }
  }
}

// ---------------- per-node gate + qe dots -> p[n][t][h] ----------------
__global__ __launch_bounds__(256) void k2_kernel(const float* __restrict__ w2,
                                                 const float* __restrict__ b2,
                                                 const int* __restrict__ node_types,
                                                 const float* __restrict__ xin, int l) {
  __shared__ float s_stq[HH * 3 * 32];
  __shared__ float s_w2[HH * 32];
  __shared__ float s_b2[HH];
  __shared__ float s_qe[12 * 256];
  int tid = threadIdx.x;
  for (int i = tid; i < HH * 3 * 32; i += 256) s_stq[i] = g_stq[i];
  for (int i = tid; i < HH * 32; i += 256) s_w2[i] = w2[l * HH * 32 + i];
  if (tid < HH) s_b2[tid] = b2[l * HH + tid];
  for (int i = tid; i < 12 * 256; i += 256) s_qe[i] = g_qe[i];
  __syncthreads();
  int warp = tid >> 5, lane = tid & 31;
  int n = blockIdx.x * 8 + warp;
  if (n >= NN) return;
  int tn = node_types[n];
  const float* Crow = g_C + (size_t)n * NC;
  const float* hrow = (l ? g_h : xin) + (size_t)n * KD;
  float hr[8];
#pragma unroll
  for (int j = 0; j < 8; ++j) hr[j] = hrow[j * 32 + lane];
#pragma unroll
  for (int h = 0; h < HH; ++h) {
    float hv = Crow[256 + h * 32 + lane];
    float th = tanhf(hv + s_stq[(h * 3 + tn) * 32 + lane]) * s_w2[h * 32 + lane];
#pragma unroll
    for (int o = 16; o; o >>= 1) th += __shfl_xor_sync(0xFFFFFFFFu, th, o);
    float at = 1.f / (1.f + expf(-(th + s_b2[h])));
#pragma unroll
    for (int t = 0; t < 3; ++t) {
      const float* qr = &s_qe[(h * 3 + t) * 256];
      float sp = 0.f;
#pragma unroll
      for (int j = 0; j < 8; ++j) sp += hr[j] * qr[j * 32 + lane];
#pragma unroll
      for (int o = 16; o; o >>= 1) sp += __shfl_xor_sync(0xFFFFFFFFu, sp, o);
      if (lane == 0) {
        float lr = sp > 0.f ? sp : 0.2f * sp;
        g_p[(n * 3 + t) * 4 + h] = lr * at;
      }
    }
  }
}

// ---------------- fused softmax + edge_feat: warp per edge ----------------
__global__ __launch_bounds__(256) void kE5_kernel(const int* __restrict__ ni) {
  __shared__ float s_w[8][256];   // [warp][pair*4 + head]
  int e = (blockIdx.x * blockDim.x + threadIdx.x) >> 5;
  int warp = (threadIdx.x >> 5);
  int lane = threadIdx.x & 31;
  if (e >= EE) return;
  int a = g_estart[e], b = g_estart[e + 1];
  {
    int h = lane & 3, pi = lane >> 2;
    float v[8];
    int mm[8];
    float mx = -1e30f;
#pragma unroll
    for (int k = 0; k < 8; ++k) {
      int i = a + k * 8 + pi;
      int m = -1;
      float val = -1e30f;
      if (i < b) {
        m = g_pbe[i];
        int nn2 = ni[m], t = g_et[m];
        val = g_p[(nn2 * 3 + t) * 4 + h];
      }
      mm[k] = m;
      v[k] = val;
      mx = fmaxf(mx, val);
    }
#pragma unroll
    for (int o = 4; o < 32; o <<= 1) mx = fmaxf(mx, __shfl_xor_sync(0xFFFFFFFFu, mx, o));
    float s = 0.f;
#pragma unroll
    for (int k = 0; k < 8; ++k) {
      if (mm[k] >= 0) { v[k] = expf(v[k] - mx); s += v[k]; }
    }
#pragma unroll
    for (int o = 4; o < 32; o <<= 1) s += __shfl_xor_sync(0xFFFFFFFFu, s, o);
    float inv = 1.f / s;
#pragma unroll
    for (int k = 0; k < 8; ++k) {
      if (mm[k] >= 0) {
        float wgt = v[k] * inv;
        g_aw[mm[k] * 4 + h] = wgt;
        s_w[warp][(k * 8 + pi) * 4 + h] = wgt;
      }
    }
  }
  __syncwarp();
  {
    int hh = lane >> 3;
    int c0 = lane * 8;
    float4 a0 = make_float4(0, 0, 0, 0), a1 = make_float4(0, 0, 0, 0);
    for (int i = a; i < b; ++i) {
      int m = g_pbe[i];
      float w = s_w[warp][(i - a) * 4 + hh];
      const float* Vr = g_C + (size_t)ni[m] * NC + c0;
      float4 v0 = *(const float4*)Vr;
      float4 v1 = *(const float4*)(Vr + 4);
      a0.x += w * v0.x; a0.y += w * v0.y; a0.z += w * v0.z; a0.w += w * v0.w;
      a1.x += w * v1.x; a1.y += w * v1.y; a1.z += w * v1.z; a1.w += w * v1.w;
    }
    float* out = g_ef + (size_t)e * 256 + c0;
    *(float4*)out = a0;
    *(float4*)(out + 4) = a1;
  }
}

// ---------------- node_feat + residual + LayerNorm ----------------
__global__ __launch_bounds__(256) void k6_kernel(const int* __restrict__ ei,
                                                 const float* __restrict__ xin,
                                                 const float* __restrict__ ln_g,
                                                 const float* __restrict__ ln_b,
                                                 float* __restrict__ dout, int l) {
  int n = (blockIdx.x * blockDim.x + threadIdx.x) >> 5;
  int lane = threadIdx.x & 31;
  if (n >= NN) return;
  const float* hin = l ? g_h : xin;
  float* hout = l ? dout : g_h;
  int hh = lane >> 3;
  int c0 = lane * 8;
  float v[8];
#pragma unroll
  for (int j = 0; j < 8; ++j) v[j] = 0.f;
  int b = g_nstart[n + 1];
  for (int i = g_nstart[n]; i < b; ++i) {
    int m = g_pbn[i];
    float w = g_aw[m * 4 + hh];
    const float* Er = g_ef + (size_t)ei[m] * 256 + c0;
    float4 e0 = *(const float4*)Er;
    float4 e1 = *(const float4*)(Er + 4);
    v[0] += w * e0.x; v[1] += w * e0.y; v[2] += w * e0.z; v[3] += w * e0.w;
    v[4] += w * e1.x; v[5] += w * e1.y; v[6] += w * e1.z; v[7] += w * e1.w;
  }
  const float* hr = hin + (size_t)n * KD + c0;
#pragma unroll
  for (int j = 0; j < 8; ++j) v[j] += hr[j];
  float s = 0.f;
#pragma unroll
  for (int j = 0; j < 8; ++j) s += v[j];
#pragma unroll
  for (int o = 16; o; o >>= 1) s += __shfl_xor_sync(0xFFFFFFFFu, s, o);
  float mu = s * (1.f / 256.f);
  float vs = 0.f;
#pragma unroll
  for (int j = 0; j < 8; ++j) { float d = v[j] - mu; vs += d * d; }
#pragma unroll
  for (int o = 16; o; o >>= 1) vs += __shfl_xor_sync(0xFFFFFFFFu, vs, o);
  float rs = rsqrtf(vs * (1.f / 256.f) + 1e-5f);
  float o8[8];
#pragma unroll
  for (int j = 0; j < 8; ++j)
    o8[j] = (v[j] - mu) * rs * ln_g[l * KD + c0 + j] + ln_b[l * KD + c0 + j];
  float* op = hout + (size_t)n * KD + c0;
  *(float4*)op = make_float4(o8[0], o8[1], o8[2], o8[3]);
  *(float4*)(op + 4) = make_float4(o8[4], o8[5], o8[6], o8[7]);
}

// ---------------- launcher (GEMM is launch #4 for ncu capture) ----------------
extern "C" void kernel_launch(void* const* d_in, const int* in_sizes, int n_in,
                              void* d_out, int out_size) {
  const float* x          = (const float*)d_in[0];
  const int*   node_types = (const int*)d_in[1];
  const int*   edge_type  = (const int*)d_in[2];
  const int*   node_idx   = (const int*)d_in[3];
  const int*   edge_idx   = (const int*)d_in[4];
  const float* tq         = (const float*)d_in[5];
  const float* w1         = (const float*)d_in[6];
  const float* b1         = (const float*)d_in[7];
  const float* w2         = (const float*)d_in[8];
  const float* b2         = (const float*)d_in[9];
  const float* wq         = (const float*)d_in[10];
  const float* wv         = (const float*)d_in[11];
  const float* ec         = (const float*)d_in[12];
  const float* ln_g       = (const float*)d_in[13];
  const float* ln_b       = (const float*)d_in[14];
  float* out = (float*)d_out;

  const int TB = 256;
  int gMax = (NN + TB - 1) / TB;
  int gM   = (MM + TB - 1) / TB;
  dim3 gg(NC / 128, (NN + 127) / 128);

  zero_counts_kernel<<<gMax, TB>>>();                                   // 1
  hist_kernel<<<gM, TB>>>(node_idx, edge_idx, edge_type);               // 2
  prepW_kernel<<<269, 384>>>(wv, w1, ec, wq, tq, b1, 0);                // 3
  gemm_tf32_kernel<<<gg, 256>>>(x, 0);                                  // 4 <- ncu
  scanA2_kernel<<<NBE + NBN, 1024>>>();                                 // 5
  scanC2_kernel<<<NBE + NBN, 1024>>>();                                 // 6
  fill_kernel<<<gM, TB>>>(node_idx, edge_idx);                          // 7
  segsort2_kernel<<<(EE + NN + TB - 1) / TB, TB>>>();                   // 8
  k2_kernel<<<(NN + 7) / 8, 256>>>(w2, b2, node_types, x, 0);           // 9
  kE5_kernel<<<(EE + 7) / 8, 256>>>(node_idx);                          // 10
  k6_kernel<<<(NN + 7) / 8, 256>>>(edge_idx, x, ln_g, ln_b, out, 0);    // 11
  prepW_kernel<<<269, 384>>>(wv, w1, ec, wq, tq, b1, 1);                // 12
  gemm_tf32_kernel<<<gg, 256>>>(x, 1);                                  // 13
  k2_kernel<<<(NN + 7) / 8, 256>>>(w2, b2, node_types, x, 1);           // 14
  kE5_kernel<<<(EE + 7) / 8, 256>>>(node_idx);                          // 15
  k6_kernel<<<(NN + 7) / 8, 256>>>(edge_idx, x, ln_g, ln_b, out, 1);    // 16
}

// round 16
// speedup vs baseline: 1.0628x; 1.0070x over previous
#include <cuda_runtime.h>
#include <cstdint>

#define NN 50000
#define EE 20000
#define MM 320000
#define HH 4
#define KD 256
#define NC 384   // 256 V | 128 hid
#define NBE 20   // ceil(EE/1024)
#define NBN 49   // ceil(NN/1024)

// ---------------- static scratch ----------------
__device__ float    g_C[(size_t)NN * NC];
__device__ float    g_h[(size_t)NN * KD];
__device__ float    g_p[NN * 12];
__device__ float    g_aw[MM * 4];
__device__ float    g_ef[(size_t)EE * 256];
__device__ int      g_et[MM];
__device__ int      g_ecnt[EE];
__device__ int      g_estart[EE + 1];
__device__ int      g_ecur[EE];
__device__ int      g_pbe[MM];
__device__ int      g_ncnt[NN];
__device__ int      g_nstart[NN + 1];
__device__ int      g_ncur[NN];
__device__ int      g_pbn[MM];
__device__ float    g_W[NC * KD];
__device__ float    g_stq[HH * 3 * 32];
__device__ float    g_qe[12 * 256];
__device__ int      g_bsum[2][64];

#define MMATF32(d, a, b0, b1) \
  asm volatile("mma.sync.aligned.m16n8k8.row.col.f32.tf32.tf32.f32 " \
    "{%0,%1,%2,%3}, {%4,%5,%6,%7}, {%8,%9}, {%0,%1,%2,%3};" \
    : "+f"((d)[0]), "+f"((d)[1]), "+f"((d)[2]), "+f"((d)[3]) \
    : "r"((a)[0]), "r"((a)[1]), "r"((a)[2]), "r"((a)[3]), "r"(b0), "r"(b1))

#define CPASYNC16(dst, src) \
  asm volatile("cp.async.cg.shared.global [%0], [%1], 16;" :: "r"(dst), "l"(src))
#define CPCOMMIT() asm volatile("cp.async.commit_group;" ::: "memory")
#define CPWAIT(n)  asm volatile("cp.async.wait_group %0;" :: "n"(n) : "memory")

// ---------------- CSR build ----------------
__global__ void zero_counts_kernel() {
  int i = blockIdx.x * blockDim.x + threadIdx.x;
  if (i < EE) g_ecnt[i] = 0;
  if (i < NN) g_ncnt[i] = 0;
}

__global__ void hist_kernel(const int* __restrict__ ni, const int* __restrict__ ei,
                            const int* __restrict__ etype) {
  int m = blockIdx.x * blockDim.x + threadIdx.x;
  if (m >= MM) return;
  int e = ei[m];
  atomicAdd(&g_ecnt[e], 1);
  atomicAdd(&g_ncnt[ni[m]], 1);
  g_et[m] = etype[e];
}

__global__ void scanA2_kernel() {
  __shared__ int sh[1024];
  int which = (blockIdx.x < NBE) ? 0 : 1;
  int bid = which ? (blockIdx.x - NBE) : blockIdx.x;
  const int* cnt = which ? g_ncnt : g_ecnt;
  int* start = which ? g_nstart : g_estart;
  int n = which ? NN : EE;
  int i = bid * 1024 + threadIdx.x;
  int v = (i < n) ? cnt[i] : 0;
  sh[threadIdx.x] = v;
  __syncthreads();
  for (int off = 1; off < 1024; off <<= 1) {
    int t = (threadIdx.x >= (unsigned)off) ? sh[threadIdx.x - off] : 0;
    __syncthreads();
    sh[threadIdx.x] += t;
    __syncthreads();
  }
  if (i < n) start[i] = sh[threadIdx.x] - v;
  if (threadIdx.x == 1023) g_bsum[which][bid] = sh[1023];
}

__global__ void scanC2_kernel() {
  int which = (blockIdx.x < NBE) ? 0 : 1;
  int bid = which ? (blockIdx.x - NBE) : blockIdx.x;
  int nb = which ? NBN : NBE;
  int* start = which ? g_nstart : g_estart;
  int* cur = which ? g_ncur : g_ecur;
  int n = which ? NN : EE;
  int off = 0;
  for (int b = 0; b < bid; ++b) off += g_bsum[which][b];
  int i = bid * 1024 + threadIdx.x;
  if (i < n) {
    int s = start[i] + off;
    start[i] = s;
    cur[i] = s;
  }
  if (bid == nb - 1 && threadIdx.x == 0)
    start[n] = off + g_bsum[which][bid];
}

__global__ void fill_kernel(const int* __restrict__ ni, const int* __restrict__ ei) {
  int m = blockIdx.x * blockDim.x + threadIdx.x;
  if (m >= MM) return;
  int pe = atomicAdd(&g_ecur[ei[m]], 1);
  g_pbe[pe] = m;
  int pn = atomicAdd(&g_ncur[ni[m]], 1);
  g_pbn[pn] = m;
}

__global__ void segsort2_kernel() {
  int s = blockIdx.x * blockDim.x + threadIdx.x;
  if (s >= EE + NN) return;
  int which = (s >= EE);
  int seg = which ? (s - EE) : s;
  const int* start = which ? g_nstart : g_estart;
  int* list = which ? g_pbn : g_pbe;
  int a = start[seg], b = start[seg + 1];
  for (int i = a; i < b - 1; ++i) {
    int mi = i, mv = list[i];
    for (int j = i + 1; j < b; ++j) {
      int v = list[j];
      if (v < mv) { mv = v; mi = j; }
    }
    list[mi] = list[i];
    list[i] = mv;
  }
}

// ---------------- merged weight prep: build_w (0..255) + qe (256..267) + stq (268) ----------------
__global__ void prepW_kernel(const float* __restrict__ wv, const float* __restrict__ w1,
                             const float* __restrict__ ec, const float* __restrict__ wq,
                             const float* __restrict__ tq, const float* __restrict__ b1,
                             int l) {
  int bid = blockIdx.x;
  int tid = threadIdx.x;
  if (bid < 256) {
    int idx = bid * 384 + tid;
    int r = idx >> 8, c = idx & 255;
    float v;
    if (r < 256) v = wv[((size_t)l * 256 + r) * 256 + c];
    else {
      int hk = r - 256;
      v = w1[(((size_t)l * HH + (hk >> 5)) * 32 + (hk & 31)) * 320 + c];
    }
    g_W[idx] = v;
  } else if (bid < 268) {
    __shared__ float s_ec[64];
    int ht = bid - 256;
    int h = ht / 3, t = ht % 3;
    if (tid < 64) s_ec[tid] = ec[((l * HH + h) * 3 + t) * 64 + tid];
    __syncthreads();
    if (tid < 256) {
      const float* wr = wq + ((size_t)(l * HH + h) * 64) * 256 + tid;
      float s = 0.f;
      for (int d = 0; d < 64; ++d) s += s_ec[d] * wr[(size_t)d * 256];
      g_qe[ht * 256 + tid] = s;
    }
  } else {
    if (tid >= 384) return;
    int h = tid / 96, rem = tid % 96, t = rem / 32, k = rem & 31;
    float s = b1[(l * HH + h) * 32 + k];
    const float* tr = tq + ((l * HH + h) * 3 + t) * 64;
    const float* wr = w1 + (((size_t)l * HH + h) * 32 + k) * 320 + 256;
    for (int d = 0; d < 64; ++d) s += tr[d] * wr[d];
    g_stq[(h * 3 + t) * 32 + k] = s;
  }
}

// ---------------- tf32 mma GEMM: g_C[N,384] = X[N,256] * g_W^T ----------------
// CTA 128(M) x 128(N), 8 warps (4x2), warp tile 32x64, k-chunk 32,
// cp.async double-buffered A and B (raw fp32 bits consumed as tf32).
__global__ __launch_bounds__(256, 2) void gemm_tf32_kernel(const float* __restrict__ xin,
                                                           int l) {
  const float* __restrict__ X = l ? g_h : xin;
  __shared__ __align__(16) uint32_t sA[2][128][36];
  __shared__ __align__(16) uint32_t sB[2][128][36];
  const int tid = threadIdx.x, lane = tid & 31, wid = tid >> 5;
  const int wm = wid >> 1, wn = wid & 1;
  const int g = lane >> 2, tg = lane & 3;
  const int row0 = blockIdx.y * 128, col0 = blockIdx.x * 128;

  // per-thread load slot: r = tid>>3 + i*32 rows? keep same mapping as before:
  // u = tid + i*256, r = u>>3, q = u&7 (4 iters for A, 4 for B)
  const int rr = tid >> 3, qq = tid & 7;

  float acc[2][8][4];
#pragma unroll
  for (int a = 0; a < 2; ++a)
#pragma unroll
    for (int b = 0; b < 8; ++b)
#pragma unroll
      for (int c = 0; c < 4; ++c) acc[a][b][c] = 0.f;

  // issue chunk 0 into buf 0
#pragma unroll
  for (int i = 0; i < 4; ++i) {
    int r = rr + i * 32;
    int gr = min(row0 + r, NN - 1);           // clamp: out-of-range rows discarded in epilogue
    uint32_t dst = (uint32_t)__cvta_generic_to_shared(&sA[0][r][qq * 4]);
    CPASYNC16(dst, X + (size_t)gr * KD + qq * 4);
  }
#pragma unroll
  for (int i = 0; i < 4; ++i) {
    int r = rr + i * 32;
    uint32_t dst = (uint32_t)__cvta_generic_to_shared(&sB[0][r][qq * 4]);
    CPASYNC16(dst, g_W + (size_t)(col0 + r) * KD + qq * 4);
  }
  CPCOMMIT();

  for (int kc = 0; kc < 8; ++kc) {
    const int buf = kc & 1;
    if (kc < 7) {  // issue next chunk into the other buffer
#pragma unroll
      for (int i = 0; i < 4; ++i) {
        int r = rr + i * 32;
        int gr = min(row0 + r, NN - 1);
        uint32_t dst = (uint32_t)__cvta_generic_to_shared(&sA[buf ^ 1][r][qq * 4]);
        CPASYNC16(dst, X + (size_t)gr * KD + (kc + 1) * 32 + qq * 4);
      }
#pragma unroll
      for (int i = 0; i < 4; ++i) {
        int r = rr + i * 32;
        uint32_t dst = (uint32_t)__cvta_generic_to_shared(&sB[buf ^ 1][r][qq * 4]);
        CPASYNC16(dst, g_W + (size_t)(col0 + r) * KD + (kc + 1) * 32 + qq * 4);
      }
      CPCOMMIT();
      CPWAIT(1);   // current buffer's group complete
    } else {
      CPWAIT(0);
    }
    __syncthreads();
#pragma unroll
    for (int ks = 0; ks < 4; ++ks) {
      const int k0 = ks * 8;
      uint32_t af[2][4], bf[8][2];
#pragma unroll
      for (int mt = 0; mt < 2; ++mt) {
        int rowA = wm * 32 + mt * 16 + g;
        af[mt][0] = sA[buf][rowA][k0 + tg];
        af[mt][1] = sA[buf][rowA + 8][k0 + tg];
        af[mt][2] = sA[buf][rowA][k0 + tg + 4];
        af[mt][3] = sA[buf][rowA + 8][k0 + tg + 4];
      }
#pragma unroll
      for (int j = 0; j < 8; ++j) {
        int rowB = wn * 64 + j * 8 + g;
        bf[j][0] = sB[buf][rowB][k0 + tg];
        bf[j][1] = sB[buf][rowB][k0 + tg + 4];
      }
#pragma unroll
      for (int mt = 0; mt < 2; ++mt)
#pragma unroll
        for (int j = 0; j < 8; ++j)
          MMATF32(acc[mt][j], af[mt], bf[j][0], bf[j][1]);
    }
    __syncthreads();   // release buf before it is overwritten two iterations later
  }

#pragma unroll
  for (int mt = 0; mt < 2; ++mt) {
    int rg = row0 + wm * 32 + mt * 16 + g;
#pragma unroll
    for (int j = 0; j < 8; ++j) {
      int c = col0 + wn * 64 + j * 8 + tg * 2;
      if (rg < NN)
        *(float2*)&g_C[(size_t)rg * NC + c] = make_float2(acc[mt][j][0], acc[mt][j][1]);
      if (rg + 8 < NN)
        *(float2*)&g_C[(size_t)(rg + 8) * NC + c] = make_float2(acc[mt][j][2], acc[mt][j][3]);
    }
  }
}

// ---------------- per-node gate + qe dots -> p[n][t][h] ----------------
__global__ __launch_bounds__(256) void k2_kernel(const float* __restrict__ w2,
                                                 const float* __restrict__ b2,
                                                 const int* __restrict__ node_types,
                                                 const float* __restrict__ xin, int l) {
  __shared__ float s_stq[HH * 3 * 32];
  __shared__ float s_w2[HH * 32];
  __shared__ float s_b2[HH];
  __shared__ float s_qe[12 * 256];
  int tid = threadIdx.x;
  for (int i = tid; i < HH * 3 * 32; i += 256) s_stq[i] = g_stq[i];
  for (int i = tid; i < HH * 32; i += 256) s_w2[i] = w2[l * HH * 32 + i];
  if (tid < HH) s_b2[tid] = b2[l * HH + tid];
  for (int i = tid; i < 12 * 256; i += 256) s_qe[i] = g_qe[i];
  __syncthreads();
  int warp = tid >> 5, lane = tid & 31;
  int n = blockIdx.x * 8 + warp;
  if (n >= NN) return;
  int tn = node_types[n];
  const float* Crow = g_C + (size_t)n * NC;
  const float* hrow = (l ? g_h : xin) + (size_t)n * KD;
  float hr[8];
#pragma unroll
  for (int j = 0; j < 8; ++j) hr[j] = hrow[j * 32 + lane];
#pragma unroll
  for (int h = 0; h < HH; ++h) {
    float hv = Crow[256 + h * 32 + lane];
    float th = tanhf(hv + s_stq[(h * 3 + tn) * 32 + lane]) * s_w2[h * 32 + lane];
#pragma unroll
    for (int o = 16; o; o >>= 1) th += __shfl_xor_sync(0xFFFFFFFFu, th, o);
    float at = 1.f / (1.f + expf(-(th + s_b2[h])));
#pragma unroll
    for (int t = 0; t < 3; ++t) {
      const float* qr = &s_qe[(h * 3 + t) * 256];
      float sp = 0.f;
#pragma unroll
      for (int j = 0; j < 8; ++j) sp += hr[j] * qr[j * 32 + lane];
#pragma unroll
      for (int o = 16; o; o >>= 1) sp += __shfl_xor_sync(0xFFFFFFFFu, sp, o);
      if (lane == 0) {
        float lr = sp > 0.f ? sp : 0.2f * sp;
        g_p[(n * 3 + t) * 4 + h] = lr * at;
      }
    }
  }
}

// ---------------- fused softmax + edge_feat: warp per edge ----------------
__global__ __launch_bounds__(256) void kE5_kernel(const int* __restrict__ ni) {
  __shared__ float s_w[8][256];
  int e = (blockIdx.x * blockDim.x + threadIdx.x) >> 5;
  int warp = (threadIdx.x >> 5);
  int lane = threadIdx.x & 31;
  if (e >= EE) return;
  int a = g_estart[e], b = g_estart[e + 1];
  {
    int h = lane & 3, pi = lane >> 2;
    float v[8];
    int mm[8];
    float mx = -1e30f;
#pragma unroll
    for (int k = 0; k < 8; ++k) {
      int i = a + k * 8 + pi;
      int m = -1;
      float val = -1e30f;
      if (i < b) {
        m = g_pbe[i];
        int nn2 = ni[m], t = g_et[m];
        val = g_p[(nn2 * 3 + t) * 4 + h];
      }
      mm[k] = m;
      v[k] = val;
      mx = fmaxf(mx, val);
    }
#pragma unroll
    for (int o = 4; o < 32; o <<= 1) mx = fmaxf(mx, __shfl_xor_sync(0xFFFFFFFFu, mx, o));
    float s = 0.f;
#pragma unroll
    for (int k = 0; k < 8; ++k) {
      if (mm[k] >= 0) { v[k] = expf(v[k] - mx); s += v[k]; }
    }
#pragma unroll
    for (int o = 4; o < 32; o <<= 1) s += __shfl_xor_sync(0xFFFFFFFFu, s, o);
    float inv = 1.f / s;
#pragma unroll
    for (int k = 0; k < 8; ++k) {
      if (mm[k] >= 0) {
        float wgt = v[k] * inv;
        g_aw[mm[k] * 4 + h] = wgt;
        s_w[warp][(k * 8 + pi) * 4 + h] = wgt;
      }
    }
  }
  __syncwarp();
  {
    int hh = lane >> 3;
    int c0 = lane * 8;
    float4 a0 = make_float4(0, 0, 0, 0), a1 = make_float4(0, 0, 0, 0);
    for (int i = a; i < b; ++i) {
      int m = g_pbe[i];
      float w = s_w[warp][(i - a) * 4 + hh];
      const float* Vr = g_C + (size_t)ni[m] * NC + c0;
      float4 v0 = *(const float4*)Vr;
      float4 v1 = *(const float4*)(Vr + 4);
      a0.x += w * v0.x; a0.y += w * v0.y; a0.z += w * v0.z; a0.w += w * v0.w;
      a1.x += w * v1.x; a1.y += w * v1.y; a1.z += w * v1.z; a1.w += w * v1.w;
    }
    float* out = g_ef + (size_t)e * 256 + c0;
    *(float4*)out = a0;
    *(float4*)(out + 4) = a1;
  }
}

// ---------------- node_feat + residual + LayerNorm ----------------
__global__ __launch_bounds__(256) void k6_kernel(const int* __restrict__ ei,
                                                 const float* __restrict__ xin,
                                                 const float* __restrict__ ln_g,
                                                 const float* __restrict__ ln_b,
                                                 float* __restrict__ dout, int l) {
  int n = (blockIdx.x * blockDim.x + threadIdx.x) >> 5;
  int lane = threadIdx.x & 31;
  if (n >= NN) return;
  const float* hin = l ? g_h : xin;
  float* hout = l ? dout : g_h;
  int hh = lane >> 3;
  int c0 = lane * 8;
  float v[8];
#pragma unroll
  for (int j = 0; j < 8; ++j) v[j] = 0.f;
  int b = g_nstart[n + 1];
  for (int i = g_nstart[n]; i < b; ++i) {
    int m = g_pbn[i];
    float w = g_aw[m * 4 + hh];
    const float* Er = g_ef + (size_t)ei[m] * 256 + c0;
    float4 e0 = *(const float4*)Er;
    float4 e1 = *(const float4*)(Er + 4);
    v[0] += w * e0.x; v[1] += w * e0.y; v[2] += w * e0.z; v[3] += w * e0.w;
    v[4] += w * e1.x; v[5] += w * e1.y; v[6] += w * e1.z; v[7] += w * e1.w;
  }
  const float* hr = hin + (size_t)n * KD + c0;
#pragma unroll
  for (int j = 0; j < 8; ++j) v[j] += hr[j];
  float s = 0.f;
#pragma unroll
  for (int j = 0; j < 8; ++j) s += v[j];
#pragma unroll
  for (int o = 16; o; o >>= 1) s += __shfl_xor_sync(0xFFFFFFFFu, s, o);
  float mu = s * (1.f / 256.f);
  float vs = 0.f;
#pragma unroll
  for (int j = 0; j < 8; ++j) { float d = v[j] - mu; vs += d * d; }
#pragma unroll
  for (int o = 16; o; o >>= 1) vs += __shfl_xor_sync(0xFFFFFFFFu, vs, o);
  float rs = rsqrtf(vs * (1.f / 256.f) + 1e-5f);
  float o8[8];
#pragma unroll
  for (int j = 0; j < 8; ++j)
    o8[j] = (v[j] - mu) * rs * ln_g[l * KD + c0 + j] + ln_b[l * KD + c0 + j];
  float* op = hout + (size_t)n * KD + c0;
  *(float4*)op = make_float4(o8[0], o8[1], o8[2], o8[3]);
  *(float4*)(op + 4) = make_float4(o8[4], o8[5], o8[6], o8[7]);
}

// ---------------- launcher (GEMM is launch #4 for ncu capture) ----------------
extern "C" void kernel_launch(void* const* d_in, const int* in_sizes, int n_in,
                              void* d_out, int out_size) {
  const float* x          = (const float*)d_in[0];
  const int*   node_types = (const int*)d_in[1];
  const int*   edge_type  = (const int*)d_in[2];
  const int*   node_idx   = (const int*)d_in[3];
  const int*   edge_idx   = (const int*)d_in[4];
  const float* tq         = (const float*)d_in[5];
  const float* w1         = (const float*)d_in[6];
  const float* b1         = (const float*)d_in[7];
  const float* w2         = (const float*)d_in[8];
  const float* b2         = (const float*)d_in[9];
  const float* wq         = (const float*)d_in[10];
  const float* wv         = (const float*)d_in[11];
  const float* ec         = (const float*)d_in[12];
  const float* ln_g       = (const float*)d_in[13];
  const float* ln_b       = (const float*)d_in[14];
  float* out = (float*)d_out;

  const int TB = 256;
  int gMax = (NN + TB - 1) / TB;
  int gM   = (MM + TB - 1) / TB;
  dim3 gg(NC / 128, (NN + 127) / 128);

  zero_counts_kernel<<<gMax, TB>>>();                                   // 1
  hist_kernel<<<gM, TB>>>(node_idx, edge_idx, edge_type);               // 2
  prepW_kernel<<<269, 384>>>(wv, w1, ec, wq, tq, b1, 0);                // 3
  gemm_tf32_kernel<<<gg, 256>>>(x, 0);                                  // 4 <- ncu
  scanA2_kernel<<<NBE + NBN, 1024>>>();                                 // 5
  scanC2_kernel<<<NBE + NBN, 1024>>>();                                 // 6
  fill_kernel<<<gM, TB>>>(node_idx, edge_idx);                          // 7
  segsort2_kernel<<<(EE + NN + TB - 1) / TB, TB>>>();                   // 8
  k2_kernel<<<(NN + 7) / 8, 256>>>(w2, b2, node_types, x, 0);           // 9
  kE5_kernel<<<(EE + 7) / 8, 256>>>(node_idx);                          // 10
  k6_kernel<<<(NN + 7) / 8, 256>>>(edge_idx, x, ln_g, ln_b, out, 0);    // 11
  prepW_kernel<<<269, 384>>>(wv, w1, ec, wq, tq, b1, 1);                // 12
  gemm_tf32_kernel<<<gg, 256>>>(x, 1);                                  // 13
  k2_kernel<<<(NN + 7) / 8, 256>>>(w2, b2, node_types, x, 1);           // 14
  kE5_kernel<<<(EE + 7) / 8, 256>>>(node_idx);                          // 15
  k6_kernel<<<(NN + 7) / 8, 256>>>(edge_idx, x, ln_g, ln_b, out, 1);    // 16
}